// round 2
// baseline (speedup 1.0000x reference)
#include <cuda_runtime.h>
#include <cstdint>

#define BN_EPS   1e-3f
#define DIN      128
#define DOUT     256
#define MT       64
#define NTHREADS 256

// smem layout (floats): sW[32768] | sA0[8192] | sA1[8192] | sScale[256] | sBias[256]
#define SMEM_FLOATS (32768 + 8192 + 8192 + 256 + 256)
#define SMEM_BYTES  (SMEM_FLOATS * 4)

__device__ __forceinline__ void ffma2(unsigned long long &d, unsigned long long a, unsigned long long b) {
    asm("fma.rn.f32x2 %0, %1, %2, %0;" : "+l"(d) : "l"(a), "l"(b));
}
__device__ __forceinline__ unsigned long long dup2(float x) {
    unsigned long long r;
    asm("mov.b64 %0, {%1, %1};" : "=l"(r) : "f"(x));
    return r;
}
__device__ __forceinline__ void unpack2(unsigned long long v, float &lo, float &hi) {
    asm("mov.b64 {%0, %1}, %2;" : "=f"(lo), "=f"(hi) : "l"(v));
}
__device__ __forceinline__ void cp_async16(float* dst_smem, const float* src) {
    unsigned s = (unsigned)__cvta_generic_to_shared(dst_smem);
    asm volatile("cp.async.cg.shared.global [%0], [%1], 16;" :: "r"(s), "l"(src));
}

__global__ __launch_bounds__(NTHREADS, 1)
void attn_transformer_kernel(const float* __restrict__ inputs,
                             const float* __restrict__ priors,
                             const float* __restrict__ W,
                             const float* __restrict__ gamma,
                             const float* __restrict__ beta,
                             const float* __restrict__ mmean,
                             const float* __restrict__ mvar,
                             float* __restrict__ out,
                             int nTiles)
{
    extern __shared__ float smem[];
    float* sW     = smem;                   // [128][256]
    float* sA0    = smem + 32768;           // [64][128]
    float* sA1    = smem + 32768 + 8192;    // [64][128]
    float* sScale = smem + 49152;           // [256]
    float* sBias  = smem + 49408;           // [256]

    const int tid   = threadIdx.x;
    const int lane  = tid & 31;
    const int warp  = tid >> 5;
    const int lane4 = lane * 4;
    const int rb    = warp * 8;

    // ---- prologue: W -> smem + first A tile, all via cp.async (one group) ----
    #pragma unroll
    for (int j = 0; j < 32; ++j) {
        int idx = tid + NTHREADS * j;               // float4 index, [0, 8192)
        cp_async16(sW + idx * 4, W + idx * 4);
    }
    if (blockIdx.x < (unsigned)nTiles) {
        const float* Abase = inputs + (size_t)blockIdx.x * MT * DIN;
        #pragma unroll
        for (int j = 0; j < 8; ++j) {
            int idx = tid + NTHREADS * j;           // float4 index, [0, 2048)
            cp_async16(sA0 + idx * 4, Abase + idx * 4);
        }
    }
    asm volatile("cp.async.commit_group;");

    // fold BN into scale/bias (inference mode)
    {
        float inv = gamma[tid] * rsqrtf(mvar[tid] + BN_EPS);
        sScale[tid] = inv;
        sBias[tid]  = beta[tid] - mmean[tid] * inv;
    }

    int p = 0;
    for (int t = blockIdx.x; t < nTiles; t += gridDim.x) {
        asm volatile("cp.async.wait_group 0;");
        __syncthreads();

        // prefetch next A tile into the other buffer
        int tn = t + gridDim.x;
        if (tn < nTiles) {
            float* sAn = p ? sA0 : sA1;
            const float* Abase = inputs + (size_t)tn * MT * DIN;
            #pragma unroll
            for (int j = 0; j < 8; ++j) {
                int idx = tid + NTHREADS * j;
                cp_async16(sAn + idx * 4, Abase + idx * 4);
            }
            asm volatile("cp.async.commit_group;");
        }

        const float* sA = p ? sA1 : sA0;

        // ---- GEMM: each thread: 8 rows (rb..rb+7) x 8 cols (lane4..+3, 128+lane4..+3)
        unsigned long long acc[8][4];
        #pragma unroll
        for (int i = 0; i < 8; ++i) {
            acc[i][0] = 0ull; acc[i][1] = 0ull; acc[i][2] = 0ull; acc[i][3] = 0ull;
        }

        #pragma unroll 2
        for (int kk = 0; kk < DIN; kk += 4) {
            float4 a4[8];
            #pragma unroll
            for (int i = 0; i < 8; ++i)
                a4[i] = *reinterpret_cast<const float4*>(&sA[(rb + i) * DIN + kk]);
            #pragma unroll
            for (int q = 0; q < 4; ++q) {
                const float* wrow = &sW[(kk + q) * DOUT];
                ulonglong2 Blo = *reinterpret_cast<const ulonglong2*>(&wrow[lane4]);
                ulonglong2 Bhi = *reinterpret_cast<const ulonglong2*>(&wrow[128 + lane4]);
                #pragma unroll
                for (int i = 0; i < 8; ++i) {
                    float av = (q == 0) ? a4[i].x : (q == 1) ? a4[i].y
                             : (q == 2) ? a4[i].z : a4[i].w;
                    unsigned long long ad = dup2(av);
                    ffma2(acc[i][0], ad, Blo.x);
                    ffma2(acc[i][1], ad, Blo.y);
                    ffma2(acc[i][2], ad, Bhi.x);
                    ffma2(acc[i][3], ad, Bhi.y);
                }
            }
        }

        // ---- epilogue: BN + prior mask (registers only) ----
        float4 scLo = *reinterpret_cast<const float4*>(&sScale[lane4]);
        float4 scHi = *reinterpret_cast<const float4*>(&sScale[128 + lane4]);
        float4 bLo  = *reinterpret_cast<const float4*>(&sBias[lane4]);
        float4 bHi  = *reinterpret_cast<const float4*>(&sBias[128 + lane4]);

        const size_t row0 = (size_t)t * MT + rb;

        float4 P[8][2];
        #pragma unroll
        for (int i = 0; i < 8; ++i) {
            const float* pr = priors + (row0 + i) * DOUT;
            P[i][0] = *reinterpret_cast<const float4*>(&pr[lane4]);
            P[i][1] = *reinterpret_cast<const float4*>(&pr[128 + lane4]);
        }

        float z[8][8];
        #pragma unroll
        for (int i = 0; i < 8; ++i) {
            float x0, x1, x2, x3, x4, x5, x6, x7;
            unpack2(acc[i][0], x0, x1);
            unpack2(acc[i][1], x2, x3);
            unpack2(acc[i][2], x4, x5);
            unpack2(acc[i][3], x6, x7);
            z[i][0] = fmaf(x0, scLo.x, bLo.x) * P[i][0].x;
            z[i][1] = fmaf(x1, scLo.y, bLo.y) * P[i][0].y;
            z[i][2] = fmaf(x2, scLo.z, bLo.z) * P[i][0].z;
            z[i][3] = fmaf(x3, scLo.w, bLo.w) * P[i][0].w;
            z[i][4] = fmaf(x4, scHi.x, bHi.x) * P[i][1].x;
            z[i][5] = fmaf(x5, scHi.y, bHi.y) * P[i][1].y;
            z[i][6] = fmaf(x6, scHi.z, bHi.z) * P[i][1].z;
            z[i][7] = fmaf(x7, scHi.w, bHi.w) * P[i][1].w;
        }

        // ---- sparsemax (Michelot fixed point), rows in pairs to pipeline shfl chains ----
        #pragma unroll
        for (int i = 0; i < 8; i += 2) {
            float* za = z[i];
            float* zb = z[i + 1];

            float sa = 0.f, sb = 0.f;
            #pragma unroll
            for (int j = 0; j < 8; ++j) { sa += za[j]; sb += zb[j]; }
            #pragma unroll
            for (int off = 16; off > 0; off >>= 1) {
                sa += __shfl_xor_sync(0xffffffffu, sa, off);
                sb += __shfl_xor_sync(0xffffffffu, sb, off);
            }
            float taua = (sa - 1.0f) * (1.0f / 256.0f);
            float taub = (sb - 1.0f) * (1.0f / 256.0f);
            float ca = 256.0f, cb = 256.0f;
            bool da = false, db = false;

            for (int it = 0; it < 300; ++it) {
                float psa = 0.f, pca = 0.f, psb = 0.f, pcb = 0.f;
                #pragma unroll
                for (int j = 0; j < 8; ++j) {
                    if (za[j] > taua) { psa += za[j]; pca += 1.0f; }
                    if (zb[j] > taub) { psb += zb[j]; pcb += 1.0f; }
                }
                #pragma unroll
                for (int off = 16; off > 0; off >>= 1) {
                    psa += __shfl_xor_sync(0xffffffffu, psa, off);
                    pca += __shfl_xor_sync(0xffffffffu, pca, off);
                    psb += __shfl_xor_sync(0xffffffffu, psb, off);
                    pcb += __shfl_xor_sync(0xffffffffu, pcb, off);
                }
                if (!da) {
                    if (pca == ca) da = true;
                    else { ca = pca; taua = (psa - 1.0f) / pca; }
                }
                if (!db) {
                    if (pcb == cb) db = true;
                    else { cb = pcb; taub = (psb - 1.0f) / pcb; }
                }
                if (da && db) break;
            }

            // write outputs (coalesced float4 x2 per row)
            float* o0 = out + (row0 + i) * DOUT;
            float* o1 = out + (row0 + i + 1) * DOUT;
            float4 v;
            v.x = fmaxf(za[0] - taua, 0.f); v.y = fmaxf(za[1] - taua, 0.f);
            v.z = fmaxf(za[2] - taua, 0.f); v.w = fmaxf(za[3] - taua, 0.f);
            *reinterpret_cast<float4*>(&o0[lane4]) = v;
            v.x = fmaxf(za[4] - taua, 0.f); v.y = fmaxf(za[5] - taua, 0.f);
            v.z = fmaxf(za[6] - taua, 0.f); v.w = fmaxf(za[7] - taua, 0.f);
            *reinterpret_cast<float4*>(&o0[128 + lane4]) = v;
            v.x = fmaxf(zb[0] - taub, 0.f); v.y = fmaxf(zb[1] - taub, 0.f);
            v.z = fmaxf(zb[2] - taub, 0.f); v.w = fmaxf(zb[3] - taub, 0.f);
            *reinterpret_cast<float4*>(&o1[lane4]) = v;
            v.x = fmaxf(zb[4] - taub, 0.f); v.y = fmaxf(zb[5] - taub, 0.f);
            v.z = fmaxf(zb[6] - taub, 0.f); v.w = fmaxf(zb[7] - taub, 0.f);
            *reinterpret_cast<float4*>(&o1[128 + lane4]) = v;
        }

        p ^= 1;
    }
}

extern "C" void kernel_launch(void* const* d_in, const int* in_sizes, int n_in,
                              void* d_out, int out_size) {
    const float* inputs = (const float*)d_in[0];
    const float* priors = (const float*)d_in[1];
    const float* W      = (const float*)d_in[2];
    const float* gamma  = (const float*)d_in[3];
    const float* beta   = (const float*)d_in[4];
    const float* mmean  = (const float*)d_in[5];
    const float* mvar   = (const float*)d_in[6];
    float* out = (float*)d_out;

    int B = in_sizes[0] / DIN;          // 262144
    int nTiles = B / MT;                // 4096

    int dev = 0;
    cudaGetDevice(&dev);
    int nsm = 0;
    cudaDeviceGetAttribute(&nsm, cudaDevAttrMultiProcessorCount, dev);
    if (nsm <= 0) nsm = 148;
    if (nsm > nTiles) nsm = nTiles;

    cudaFuncSetAttribute(attn_transformer_kernel,
                         cudaFuncAttributeMaxDynamicSharedMemorySize, SMEM_BYTES);

    attn_transformer_kernel<<<nsm, NTHREADS, SMEM_BYTES>>>(
        inputs, priors, W, gamma, beta, mmean, mvar, out, nTiles);
}

// round 7
// speedup vs baseline: 1.0252x; 1.0252x over previous
#include <cuda_runtime.h>
#include <cstdint>

#define BN_EPS   1e-3f
#define DIN      128
#define DOUT     256
#define MT       64
#define NTHREADS 256

// smem (floats): sW[32768] | sA[8 warps][2 bufs][1024] | sScale[256] | sBias[256]
#define SMEM_FLOATS (32768 + 16384 + 256 + 256)
#define SMEM_BYTES  (SMEM_FLOATS * 4)

__device__ __forceinline__ void ffma2(unsigned long long &d, unsigned long long a, unsigned long long b) {
    asm("fma.rn.f32x2 %0, %1, %2, %0;" : "+l"(d) : "l"(a), "l"(b));
}
__device__ __forceinline__ unsigned long long dup2(float x) {
    unsigned long long r;
    asm("mov.b64 %0, {%1, %1};" : "=l"(r) : "f"(x));
    return r;
}
__device__ __forceinline__ void unpack2(unsigned long long v, float &lo, float &hi) {
    asm("mov.b64 {%0, %1}, %2;" : "=f"(lo), "=f"(hi) : "l"(v));
}
__device__ __forceinline__ void cp_async16(float* dst_smem, const float* src) {
    unsigned s = (unsigned)__cvta_generic_to_shared(dst_smem);
    asm volatile("cp.async.cg.shared.global [%0], [%1], 16;" :: "r"(s), "l"(src));
}
#define CP_COMMIT() asm volatile("cp.async.commit_group;")
#define CP_WAIT1()  asm volatile("cp.async.wait_group 1;")

__global__ __launch_bounds__(NTHREADS, 1)
void attn_transformer_kernel(const float* __restrict__ inputs,
                             const float* __restrict__ priors,
                             const float* __restrict__ W,
                             const float* __restrict__ gamma,
                             const float* __restrict__ beta,
                             const float* __restrict__ mmean,
                             const float* __restrict__ mvar,
                             float* __restrict__ out,
                             int nTiles)
{
    extern __shared__ float smem[];
    float* sW     = smem;                    // [128][256]
    float* sAbase = smem + 32768;            // [8 warps][2][8][128]
    float* sScale = smem + 32768 + 16384;    // [256]
    float* sBias  = sScale + 256;            // [256]

    const int tid   = threadIdx.x;
    const int lane  = tid & 31;
    const int warp  = tid >> 5;
    const int lane4 = lane * 4;

    float* sA0 = sAbase + warp * 2048;       // this warp's buffer 0
    float* sA1 = sA0 + 1024;                 // buffer 1

    // ---- prologue ----
    // group g0: W -> smem (all threads cooperate)
    #pragma unroll
    for (int j = 0; j < 32; ++j) {
        int idx = tid + NTHREADS * j;                // float4 idx [0,8192)
        cp_async16(sW + idx * 4, W + idx * 4);
    }
    CP_COMMIT();
    // group g1: this warp's first A tile (8 rows x 128 floats = 256 x 16B chunks)
    {
        const float* Abase = inputs + ((size_t)blockIdx.x * MT + warp * 8) * DIN;
        #pragma unroll
        for (int j = 0; j < 8; ++j) {
            int c = lane + 32 * j;                   // 16B chunk [0,256)
            cp_async16(sA0 + c * 4, Abase + c * 4);
        }
    }
    CP_COMMIT();

    // fold BN into scale/bias
    {
        float inv = gamma[tid] * rsqrtf(mvar[tid] + BN_EPS);
        sScale[tid] = inv;
        sBias[tid]  = beta[tid] - mmean[tid] * inv;
    }

    CP_WAIT1();          // g0 (W) done per-thread; g1 may fly
    __syncthreads();     // the ONLY CTA-wide barrier: W visible to all warps

    // loop-invariant epilogue constants
    float4 scLo = *reinterpret_cast<const float4*>(&sScale[lane4]);
    float4 scHi = *reinterpret_cast<const float4*>(&sScale[128 + lane4]);
    float4 bLo  = *reinterpret_cast<const float4*>(&sBias[lane4]);
    float4 bHi  = *reinterpret_cast<const float4*>(&sBias[128 + lane4]);

    int p = 0;
    for (int t = blockIdx.x; t < nTiles; t += gridDim.x) {
        // prefetch this warp's rows of the next tile into the other buffer
        int tn = t + gridDim.x;
        if (tn < nTiles) {
            float* sAn = p ? sA0 : sA1;
            const float* Abase = inputs + ((size_t)tn * MT + warp * 8) * DIN;
            #pragma unroll
            for (int j = 0; j < 8; ++j) {
                int c = lane + 32 * j;
                cp_async16(sAn + c * 4, Abase + c * 4);
            }
        }
        CP_COMMIT();                         // (possibly empty group — keeps count uniform)
        CP_WAIT1();                          // current tile's copies done (per-warp)
        __syncwarp();

        const float* sA = p ? sA1 : sA0;

        // ---- GEMM: 8 rows x 8 cols per thread, packed f32x2 FFMA ----
        unsigned long long acc[8][4];
        #pragma unroll
        for (int i = 0; i < 8; ++i) {
            acc[i][0] = 0ull; acc[i][1] = 0ull; acc[i][2] = 0ull; acc[i][3] = 0ull;
        }

        #pragma unroll 2
        for (int kk = 0; kk < DIN; kk += 4) {
            float4 a4[8];
            #pragma unroll
            for (int i = 0; i < 8; ++i)
                a4[i] = *reinterpret_cast<const float4*>(&sA[i * DIN + kk]);
            #pragma unroll
            for (int q = 0; q < 4; ++q) {
                const float* wrow = &sW[(kk + q) * DOUT];
                ulonglong2 Blo = *reinterpret_cast<const ulonglong2*>(&wrow[lane4]);
                ulonglong2 Bhi = *reinterpret_cast<const ulonglong2*>(&wrow[128 + lane4]);
                #pragma unroll
                for (int i = 0; i < 8; ++i) {
                    float av = (q == 0) ? a4[i].x : (q == 1) ? a4[i].y
                             : (q == 2) ? a4[i].z : a4[i].w;
                    unsigned long long ad = dup2(av);
                    ffma2(acc[i][0], ad, Blo.x);
                    ffma2(acc[i][1], ad, Blo.y);
                    ffma2(acc[i][2], ad, Bhi.x);
                    ffma2(acc[i][3], ad, Bhi.y);
                }
            }
        }

        // ---- epilogue: BN + prior mask ----
        const size_t row0 = (size_t)t * MT + warp * 8;

        float4 P[8][2];
        #pragma unroll
        for (int i = 0; i < 8; ++i) {
            const float* pr = priors + (row0 + i) * DOUT;
            P[i][0] = *reinterpret_cast<const float4*>(&pr[lane4]);
            P[i][1] = *reinterpret_cast<const float4*>(&pr[128 + lane4]);
        }

        float z[8][8];
        #pragma unroll
        for (int i = 0; i < 8; ++i) {
            float x0, x1, x2, x3, x4, x5, x6, x7;
            unpack2(acc[i][0], x0, x1);
            unpack2(acc[i][1], x2, x3);
            unpack2(acc[i][2], x4, x5);
            unpack2(acc[i][3], x6, x7);
            z[i][0] = fmaf(x0, scLo.x, bLo.x) * P[i][0].x;
            z[i][1] = fmaf(x1, scLo.y, bLo.y) * P[i][0].y;
            z[i][2] = fmaf(x2, scLo.z, bLo.z) * P[i][0].z;
            z[i][3] = fmaf(x3, scLo.w, bLo.w) * P[i][0].w;
            z[i][4] = fmaf(x4, scHi.x, bHi.x) * P[i][1].x;
            z[i][5] = fmaf(x5, scHi.y, bHi.y) * P[i][1].y;
            z[i][6] = fmaf(x6, scHi.z, bHi.z) * P[i][1].z;
            z[i][7] = fmaf(x7, scHi.w, bHi.w) * P[i][1].w;
        }

        // ---- sparsemax (Michelot fixed point), rows in pairs ----
        #pragma unroll
        for (int i = 0; i < 8; i += 2) {
            float* za = z[i];
            float* zb = z[i + 1];

            float sa = 0.f, sb = 0.f;
            #pragma unroll
            for (int j = 0; j < 8; ++j) { sa += za[j]; sb += zb[j]; }
            #pragma unroll
            for (int off = 16; off > 0; off >>= 1) {
                sa += __shfl_xor_sync(0xffffffffu, sa, off);
                sb += __shfl_xor_sync(0xffffffffu, sb, off);
            }
            float taua = (sa - 1.0f) * (1.0f / 256.0f);
            float taub = (sb - 1.0f) * (1.0f / 256.0f);
            float ca = 256.0f, cb = 256.0f;
            bool da = false, db = false;

            for (int it = 0; it < 64; ++it) {
                float psa = 0.f, pca = 0.f, psb = 0.f, pcb = 0.f;
                #pragma unroll
                for (int j = 0; j < 8; ++j) {
                    if (za[j] > taua) { psa += za[j]; pca += 1.0f; }
                    if (zb[j] > taub) { psb += zb[j]; pcb += 1.0f; }
                }
                #pragma unroll
                for (int off = 16; off > 0; off >>= 1) {
                    psa += __shfl_xor_sync(0xffffffffu, psa, off);
                    pca += __shfl_xor_sync(0xffffffffu, pca, off);
                    psb += __shfl_xor_sync(0xffffffffu, psb, off);
                    pcb += __shfl_xor_sync(0xffffffffu, pcb, off);
                }
                if (!da) {
                    if (pca == ca) da = true;
                    else { ca = pca; taua = (psa - 1.0f) / pca; }
                }
                if (!db) {
                    if (pcb == cb) db = true;
                    else { cb = pcb; taub = (psb - 1.0f) / pcb; }
                }
                if (da && db) break;
            }

            float* o0 = out + (row0 + i) * DOUT;
            float* o1 = out + (row0 + i + 1) * DOUT;
            float4 v;
            v.x = fmaxf(za[0] - taua, 0.f); v.y = fmaxf(za[1] - taua, 0.f);
            v.z = fmaxf(za[2] - taua, 0.f); v.w = fmaxf(za[3] - taua, 0.f);
            *reinterpret_cast<float4*>(&o0[lane4]) = v;
            v.x = fmaxf(za[4] - taua, 0.f); v.y = fmaxf(za[5] - taua, 0.f);
            v.z = fmaxf(za[6] - taua, 0.f); v.w = fmaxf(za[7] - taua, 0.f);
            *reinterpret_cast<float4*>(&o0[128 + lane4]) = v;
            v.x = fmaxf(zb[0] - taub, 0.f); v.y = fmaxf(zb[1] - taub, 0.f);
            v.z = fmaxf(zb[2] - taub, 0.f); v.w = fmaxf(zb[3] - taub, 0.f);
            *reinterpret_cast<float4*>(&o1[lane4]) = v;
            v.x = fmaxf(zb[4] - taub, 0.f); v.y = fmaxf(zb[5] - taub, 0.f);
            v.z = fmaxf(zb[6] - taub, 0.f); v.w = fmaxf(zb[7] - taub, 0.f);
            *reinterpret_cast<float4*>(&o1[128 + lane4]) = v;
        }

        p ^= 1;
    }
}

extern "C" void kernel_launch(void* const* d_in, const int* in_sizes, int n_in,
                              void* d_out, int out_size) {
    const float* inputs = (const float*)d_in[0];
    const float* priors = (const float*)d_in[1];
    const float* W      = (const float*)d_in[2];
    const float* gamma  = (const float*)d_in[3];
    const float* beta   = (const float*)d_in[4];
    const float* mmean  = (const float*)d_in[5];
    const float* mvar   = (const float*)d_in[6];
    float* out = (float*)d_out;

    int B = in_sizes[0] / DIN;          // 262144
    int nTiles = B / MT;                // 4096

    int dev = 0;
    cudaGetDevice(&dev);
    int nsm = 0;
    cudaDeviceGetAttribute(&nsm, cudaDevAttrMultiProcessorCount, dev);
    if (nsm <= 0) nsm = 148;
    if (nsm > nTiles) nsm = nTiles;

    cudaFuncSetAttribute(attn_transformer_kernel,
                         cudaFuncAttributeMaxDynamicSharedMemorySize, SMEM_BYTES);

    attn_transformer_kernel<<<nsm, NTHREADS, SMEM_BYTES>>>(
        inputs, priors, W, gamma, beta, mmean, mvar, out, nTiles);
}